// round 16
// baseline (speedup 1.0000x reference)
#include <cuda_runtime.h>
#include <cuda_bf16.h>
#include <math.h>
#include <stdint.h>

#define PP 4
#define BB 128
#define DD 512
#define NN 32768
#define KK 10
#define NT 128
#define NTILES (NN/NT)   /* 256 */
#define SCALE_C 10.0f
#define INV_TEMP 2.0f
#define SIM_THR 0.7f
#define KLW 0.4916666666666667f
#define NEG_INF_F (-1e30f)

/* sim (tf32 legacy) geometry */
#define RS 20
#define STAGE_F (BB*RS)
#define NSTG 4
#define DSMEM_BYTES (2*NSTG*STAGE_F*4)   /* 81920 */

/* neg (bf16) geometry: 64B smem rows (one K=32 chunk), SW64 swizzle */
#define KCH 32
#define NCH (DD/KCH)            /* 16 chunks */
#define SRB 64                  /* smem row bytes */
#define ATILE (BB*SRB)          /* 8192 */
#define BTILE (BB*SRB)

// ---------------- device scratch ----------------
__device__ float g_img[PP*BB*DD];
__device__ float g_txt[PP*BB*DD];
__device__ __nv_bfloat16 g_featbf[PP*BB*DD];
__device__ float g_fn2[PP*BB];
__device__ float g_simpart[2*PP*4*BB*BB];
__device__ unsigned char g_negmask[NN];
__device__ float g_partial[PP*NTILES*BB];
__device__ float g_negsum[PP*BB];
__device__ float g_possum[PP*BB];
__device__ float g_alignpart[PP];

// ---------------- helpers ----------------
__device__ __forceinline__ float blockReduceSum(float v) {
    __shared__ float sh[32];
    int lane = threadIdx.x & 31, w = threadIdx.x >> 5;
    #pragma unroll
    for (int o = 16; o; o >>= 1) v += __shfl_down_sync(0xffffffffu, v, o);
    if (!lane) sh[w] = v;
    __syncthreads();
    int nw = (blockDim.x + 31) >> 5;
    v = (threadIdx.x < nw) ? sh[threadIdx.x] : 0.f;
    if (!w) {
        #pragma unroll
        for (int o = 16; o; o >>= 1) v += __shfl_down_sync(0xffffffffu, v, o);
    }
    __syncthreads();
    return v;  // valid on thread 0
}

__device__ __forceinline__ float tf32r(float x) {
    asm("cvt.rna.tf32.f32 %0, %0;" : "+f"(x));
    return x;
}

__device__ __forceinline__ uint32_t smem_u32(const void* p) {
    uint32_t a;
    asm("{ .reg .u64 t; cvta.to.shared.u64 t, %1; cvt.u32.u64 %0, t; }"
        : "=r"(a) : "l"(p));
    return a;
}

__device__ __forceinline__ void cp16(uint32_t dst, const void* src) {
    asm volatile("cp.async.cg.shared.global [%0], [%1], 16;\n" :: "r"(dst), "l"(src));
}

__device__ __forceinline__ void ldsm4(uint32_t* r, uint32_t addr) {
    asm volatile("ldmatrix.sync.aligned.m8n8.x4.shared.b16 {%0,%1,%2,%3}, [%4];\n"
                 : "=r"(r[0]), "=r"(r[1]), "=r"(r[2]), "=r"(r[3]) : "r"(addr));
}

__device__ __forceinline__ void mma_tf32(float* c, const uint32_t* a, const uint32_t* b) {
    asm volatile(
        "mma.sync.aligned.m16n8k8.row.col.f32.tf32.tf32.f32 "
        "{%0,%1,%2,%3}, {%4,%5,%6,%7}, {%8,%9}, {%0,%1,%2,%3};\n"
        : "+f"(c[0]), "+f"(c[1]), "+f"(c[2]), "+f"(c[3])
        : "r"(a[0]), "r"(a[1]), "r"(a[2]), "r"(a[3]), "r"(b[0]), "r"(b[1]));
}

__device__ __forceinline__ void mma_bf16(float* c, const uint32_t* a, const uint32_t* b) {
    asm volatile(
        "mma.sync.aligned.m16n8k16.row.col.f32.bf16.bf16.f32 "
        "{%0,%1,%2,%3}, {%4,%5,%6,%7}, {%8,%9}, {%0,%1,%2,%3};\n"
        : "+f"(c[0]), "+f"(c[1]), "+f"(c[2]), "+f"(c[3])
        : "r"(a[0]), "r"(a[1]), "r"(a[2]), "r"(a[3]), "r"(b[0]), "r"(b[1]));
}

__device__ __forceinline__ uint32_t bf2(float hi, float lo) {
    uint32_t r;
    asm("cvt.rn.bf16x2.f32 %0, %1, %2;" : "=r"(r) : "f"(hi), "f"(lo));
    return r;
}

__device__ __forceinline__ void sts128(uint32_t addr, uint32_t w0, uint32_t w1,
                                       uint32_t w2, uint32_t w3) {
    asm volatile("st.shared.v4.b32 [%0], {%1,%2,%3,%4};"
                 :: "r"(addr), "r"(w0), "r"(w1), "r"(w2), "r"(w3));
}

// fast exp(-SCALE * sqrt(max(pd2, eps))): sqrt via x * rsqrt(x)
__device__ __forceinline__ float edist(float pd2) {
    float x = fmaxf(pd2, 1e-12f);
    return __expf(-SCALE_C * (x * __frsqrt_rn(x)));
}

// ---------------- 1. normalize rows + fn2 + negmask + featbf ----------------
__global__ void prep_kernel(const float* __restrict__ feat,
                            const float* __restrict__ text) {
    int mi = blockIdx.x * 128 + threadIdx.x;
    if (mi < NN) g_negmask[mi] = 1;

    int pb = blockIdx.x;
    int p = pb / BB, b = pb % BB;
    const float* f = feat + (size_t)pb * DD;
    const float* t = text + ((size_t)b * PP + p) * DD;
    float s1 = 0.f, s2 = 0.f;
    for (int d = threadIdx.x; d < DD; d += 128) {
        float v = f[d]; s1 += v * v;
        float w = t[d]; s2 += w * w;
        g_featbf[(size_t)pb * DD + d] = __float2bfloat16(v);
    }
    __shared__ float inv1, inv2;
    float r1 = blockReduceSum(s1);
    if (threadIdx.x == 0) {
        g_fn2[pb] = r1;
        inv1 = 1.f / fmaxf(sqrtf(r1), 1e-12f);
    }
    float r2 = blockReduceSum(s2);
    if (threadIdx.x == 0) inv2 = 1.f / fmaxf(sqrtf(r2), 1e-12f);
    __syncthreads();
    for (int d = threadIdx.x; d < DD; d += 128) {
        g_img[(size_t)pb * DD + d] = tf32r(f[d] * inv1);
        g_txt[(size_t)pb * DD + d] = tf32r(t[d] * inv2);
    }
}

// ---------------- 2. neg mask scatter ----------------
__global__ void mask_scatter_kernel(const int* __restrict__ ci,
                                    const int* __restrict__ pos) {
    int i = blockIdx.x * 256 + threadIdx.x;
    if (i < BB * KK)            g_negmask[ci[i]] = 0;
    else if (i < BB * KK + BB)  g_negmask[pos[i - BB * KK]] = 0;
}

// ---------------- 3. NEG GEMM: bf16 mma, cp.async A (prebf16) + SW64 ---------
__global__ __launch_bounds__(256, 2) void neg_bf16_kernel(
        const float* __restrict__ centers) {
    __shared__ __align__(16) char Asm[3 * ATILE];
    __shared__ __align__(16) char Bsm[2 * BTILE];
    __shared__ float redp[4][BB];
    __shared__ float cn2s[BB];

    int p = blockIdx.y, n0 = blockIdx.x * NT;
    const __nv_bfloat16* Af = g_featbf + (size_t)p * BB * DD;
    const float* Bp = centers + ((size_t)p * NN + n0) * DD;

    int t = threadIdx.x, lane = t & 31, wid = t >> 5;
    int g = lane >> 2, tig = lane & 3;
    int warpM = (wid >> 2) * 64;
    int warpN = (wid & 3) * 32;
    int q = lane >> 3, r = lane & 7;

    uint32_t sA = smem_u32(Asm), sB = smem_u32(Bsm);

    int srow = t >> 1, half = t & 1;
    uint32_t swrow = (uint32_t)((srow & 6) << 3);
    uint32_t dA0 = sA + srow * SRB + (((2 * half) * 16) ^ swrow);
    uint32_t dA1 = sA + srow * SRB + (((2 * half + 1) * 16) ^ swrow);
    uint32_t dB0 = sB + srow * SRB + (((2 * half) * 16) ^ swrow);
    uint32_t dB1 = sB + srow * SRB + (((2 * half + 1) * 16) ^ swrow);
    const char* gAs = (const char*)Af + ((size_t)srow * DD + half * 16) * 2;
    const float4* gB = (const float4*)(Bp + (size_t)srow * DD + half * 16);

    int rowa = warpM + (q & 1) * 8 + r;
    uint32_t aswz = (uint32_t)((rowa & 6) << 3);
    uint32_t aBase = sA + rowa * SRB;
    int rowb = warpN + (q >> 1) * 8 + r;
    uint32_t bswz = (uint32_t)((rowb & 6) << 3);
    uint32_t bBase = sB + rowb * SRB;

    float acc[4][4][4];
    #pragma unroll
    for (int i = 0; i < 4; i++)
        #pragma unroll
        for (int j = 0; j < 4; j++)
            #pragma unroll
            for (int z = 0; z < 4; z++) acc[i][j][z] = 0.f;

    #pragma unroll
    for (int c0 = 0; c0 < 2; c0++) {
        const char* s = gAs + c0 * 64;
        cp16(dA0 + c0 * ATILE, s);
        cp16(dA1 + c0 * ATILE, s + 16);
        asm volatile("cp.async.commit_group;\n");
    }
    float4 rb[4];
    #pragma unroll
    for (int i = 0; i < 4; i++) rb[i] = gB[i];

    float csq = 0.f;
    for (int c = 0; c < NCH; c++) {
        int bbuf = c & 1;
        uint32_t bo = (uint32_t)(bbuf * BTILE);
        sts128(dB0 + bo, bf2(rb[0].y, rb[0].x), bf2(rb[0].w, rb[0].z),
                         bf2(rb[1].y, rb[1].x), bf2(rb[1].w, rb[1].z));
        sts128(dB1 + bo, bf2(rb[2].y, rb[2].x), bf2(rb[2].w, rb[2].z),
                         bf2(rb[3].y, rb[3].x), bf2(rb[3].w, rb[3].z));
        #pragma unroll
        for (int i = 0; i < 4; i++)
            csq += rb[i].x*rb[i].x + rb[i].y*rb[i].y + rb[i].z*rb[i].z + rb[i].w*rb[i].w;

        asm volatile("cp.async.wait_group 1;\n");
        __syncthreads();

        if (c + 2 < NCH) {
            uint32_t ao2 = (uint32_t)(((c + 2) % 3) * ATILE);
            const char* s = gAs + (c + 2) * 64;
            cp16(dA0 + ao2, s);
            cp16(dA1 + ao2, s + 16);
        }
        asm volatile("cp.async.commit_group;\n");

        if (c + 1 < NCH) {
            #pragma unroll
            for (int i = 0; i < 4; i++) rb[i] = gB[(c + 1) * 8 + i];
        }

        uint32_t ao = (uint32_t)((c % 3) * ATILE);
        #pragma unroll
        for (int ks = 0; ks < 2; ks++) {
            uint32_t af_[4][4], bf_[4][2];
            uint32_t aoff = ao + ((((q >> 1) * 16) + ks * 32) ^ aswz);
            #pragma unroll
            for (int mt = 0; mt < 4; mt++)
                ldsm4(af_[mt], aBase + aoff + mt * (16 * SRB));
            uint32_t boff = bo + ((((q & 1) * 16) + ks * 32) ^ bswz);
            uint32_t tmp[4];
            ldsm4(tmp, bBase + boff);
            bf_[0][0]=tmp[0]; bf_[0][1]=tmp[1]; bf_[1][0]=tmp[2]; bf_[1][1]=tmp[3];
            ldsm4(tmp, bBase + boff + 16 * SRB);
            bf_[2][0]=tmp[0]; bf_[2][1]=tmp[1]; bf_[3][0]=tmp[2]; bf_[3][1]=tmp[3];
            #pragma unroll
            for (int mt = 0; mt < 4; mt++)
                #pragma unroll
                for (int nt = 0; nt < 4; nt++)
                    mma_bf16(acc[mt][nt], af_[mt], bf_[nt]);
        }
    }
    __syncthreads();

    csq += __shfl_xor_sync(0xffffffffu, csq, 1);
    if (half == 0) cn2s[srow] = csq;
    __syncthreads();

    float rsum[4][2];
    #pragma unroll
    for (int mt = 0; mt < 4; mt++) { rsum[mt][0] = 0.f; rsum[mt][1] = 0.f; }

    float f0[4], f1[4];
    #pragma unroll
    for (int mt = 0; mt < 4; mt++) {
        f0[mt] = g_fn2[p * BB + warpM + mt * 16 + g];
        f1[mt] = g_fn2[p * BB + warpM + mt * 16 + g + 8];
    }
    #pragma unroll
    for (int nt = 0; nt < 4; nt++) {
        int c0 = warpN + nt * 8 + 2 * tig;
        int c1 = c0 + 1;
        bool m0 = g_negmask[n0 + c0] != 0;
        bool m1 = g_negmask[n0 + c1] != 0;
        float cn0 = cn2s[c0], cn1 = cn2s[c1];
        #pragma unroll
        for (int mt = 0; mt < 4; mt++) {
            if (m0) {
                rsum[mt][0] += edist(f0[mt] + cn0 - 2.f * acc[mt][nt][0]);
                rsum[mt][1] += edist(f1[mt] + cn0 - 2.f * acc[mt][nt][2]);
            }
            if (m1) {
                rsum[mt][0] += edist(f0[mt] + cn1 - 2.f * acc[mt][nt][1]);
                rsum[mt][1] += edist(f1[mt] + cn1 - 2.f * acc[mt][nt][3]);
            }
        }
    }
    #pragma unroll
    for (int mt = 0; mt < 4; mt++) {
        #pragma unroll
        for (int h = 0; h < 2; h++) {
            float v = rsum[mt][h];
            v += __shfl_xor_sync(0xffffffffu, v, 1);
            v += __shfl_xor_sync(0xffffffffu, v, 2);
            rsum[mt][h] = v;
        }
    }
    if (tig == 0) {
        #pragma unroll
        for (int mt = 0; mt < 4; mt++) {
            redp[wid & 3][warpM + mt * 16 + g]     = rsum[mt][0];
            redp[wid & 3][warpM + mt * 16 + g + 8] = rsum[mt][1];
        }
    }
    __syncthreads();
    if (t < BB) {
        float s = redp[0][t] + redp[1][t] + redp[2][t] + redp[3][t];
        g_partial[((size_t)p * NTILES + blockIdx.x) * BB + t] = s;
    }
}

// ---------------- 3s. sim GEMM (tf32 legacy path, K-split x4) ----------------
__global__ __launch_bounds__(256) void sim_gemm_kernel() {
    extern __shared__ __align__(16) float dyn[];
    float* AsBase = dyn;
    float* BsBase = dyn + NSTG * STAGE_F;

    int p = blockIdx.y;
    const int NC = 8;
    int sel = blockIdx.x >> 2, kz = blockIdx.x & 3;
    const float* src = (sel ? g_txt : g_img) + (size_t)p * BB * DD + kz * 128;
    const float* Aptr = src;
    const float* Bptr = src;
    float* partdst = g_simpart + (size_t)((sel * PP + p) * 4 + kz) * BB * BB;

    int t = threadIdx.x;
    int lane = t & 31, wid = t >> 5;
    int g = lane >> 2, tig = lane & 3;
    int warpM = (wid >> 2) * 64;
    int warpN = (wid & 3) * 32;
    int q = lane >> 3, r = lane & 7;

    uint32_t sA = smem_u32(AsBase), sB = smem_u32(BsBase);
    uint32_t aRM = sA + (((warpM + (q & 1) * 8 + r) * RS + (q >> 1) * 4) << 2);
    uint32_t bRM = sB + (((warpN + (q >> 1) * 8 + r) * RS + (q & 1) * 4) << 2);

    int srow = t >> 1, kh = t & 1;
    uint32_t dA = sA + ((srow * RS + kh * 8) << 2);
    uint32_t dB = sB + ((srow * RS + kh * 8) << 2);
    const float* gA = Aptr + (size_t)srow * DD + kh * 8;
    const float* gB = Bptr + (size_t)srow * DD + kh * 8;

    float acc[4][4][4];
    #pragma unroll
    for (int i = 0; i < 4; i++)
        #pragma unroll
        for (int j = 0; j < 4; j++)
            #pragma unroll
            for (int z = 0; z < 4; z++) acc[i][j][z] = 0.f;

    #pragma unroll
    for (int s = 0; s < NSTG - 1; s++) {
        uint32_t off = (uint32_t)(s * STAGE_F) << 2;
        const float* gA2 = gA + s * 16;
        const float* gB2 = gB + s * 16;
        cp16(dA + off, gA2); cp16(dA + off + 16, gA2 + 4);
        cp16(dB + off, gB2); cp16(dB + off + 16, gB2 + 4);
        asm volatile("cp.async.commit_group;\n");
    }

    for (int c = 0; c < NC; c++) {
        asm volatile("cp.async.wait_group 2;\n");
        __syncthreads();

        if (c + NSTG - 1 < NC) {
            int s = c + NSTG - 1;
            uint32_t off = (uint32_t)((s & (NSTG - 1)) * STAGE_F) << 2;
            const float* gA2 = gA + s * 16;
            const float* gB2 = gB + s * 16;
            cp16(dA + off, gA2); cp16(dA + off + 16, gA2 + 4);
            cp16(dB + off, gB2); cp16(dB + off + 16, gB2 + 4);
        }
        asm volatile("cp.async.commit_group;\n");

        int buf = c & (NSTG - 1);
        uint32_t soff = (uint32_t)(buf * STAGE_F) << 2;
        #pragma unroll
        for (int ks = 0; ks < 2; ks++) {
            uint32_t koff = soff + ks * 32;
            uint32_t af[4][4], bf[4][2];
            #pragma unroll
            for (int mt = 0; mt < 4; mt++)
                ldsm4(af[mt], aRM + koff + mt * (16 * RS * 4));
            {
                uint32_t tmp[4];
                ldsm4(tmp, bRM + koff);
                bf[0][0]=tmp[0]; bf[0][1]=tmp[1]; bf[1][0]=tmp[2]; bf[1][1]=tmp[3];
                ldsm4(tmp, bRM + koff + 16 * RS * 4);
                bf[2][0]=tmp[0]; bf[2][1]=tmp[1]; bf[3][0]=tmp[2]; bf[3][1]=tmp[3];
            }
            #pragma unroll
            for (int mt = 0; mt < 4; mt++)
                #pragma unroll
                for (int nt = 0; nt < 4; nt++)
                    mma_tf32(acc[mt][nt], af[mt], bf[nt]);
        }
    }
    __syncthreads();

    #pragma unroll
    for (int mt = 0; mt < 4; mt++) {
        int r0 = warpM + mt * 16 + g;
        int r1 = r0 + 8;
        #pragma unroll
        for (int nt = 0; nt < 4; nt++) {
            int c0 = warpN + nt * 8 + 2 * tig;
            partdst[r0 * BB + c0]     = acc[mt][nt][0];
            partdst[r0 * BB + c0 + 1] = acc[mt][nt][1];
            partdst[r1 * BB + c0]     = acc[mt][nt][2];
            partdst[r1 * BB + c0 + 1] = acc[mt][nt][3];
        }
    }
}

// ---------------- 4. fused combine + valid + align KL ----------------
// grid PP, 1024 threads: thread = (row = t>>3, sub = t&7); each thread owns
// 16 columns of its row, sums K-split partials ONCE into registers, computes
// valid flags (phase A), then LSE + KL (phase B). Writes g_alignpart[p].
__global__ __launch_bounds__(1024) void fused_align_kernel() {
    int p = blockIdx.x;
    int t = threadIdx.x;
    int row = t >> 3, sub = t & 7;
    __shared__ unsigned char validsm[BB];
    __shared__ float rowklsm[BB];
    __shared__ float srkl;

    const float* ib = g_simpart + (size_t)(p * 4) * BB * BB;
    const float* tb = g_simpart + (size_t)((PP + p) * 4) * BB * BB;
    const size_t PL = (size_t)BB * BB;

    float im[16], tx[16];
    int flag = 0;
    #pragma unroll
    for (int j = 0; j < 16; j++) {
        size_t off = (size_t)row * BB + sub * 16 + j;
        im[j] = (ib[off] + ib[off + PL] + ib[off + 2*PL] + ib[off + 3*PL]) * INV_TEMP;
        tx[j] = (tb[off] + tb[off + PL] + tb[off + 2*PL] + tb[off + 3*PL]) * INV_TEMP;
        if (im[j] > SIM_THR && tx[j] > SIM_THR) flag = 1;
    }
    #pragma unroll
    for (int o = 4; o; o >>= 1) flag |= __shfl_down_sync(0xffffffffu, flag, o, 8);
    if (sub == 0) validsm[row] = (unsigned char)flag;
    __syncthreads();

    unsigned char vc[16];
    #pragma unroll
    for (int j = 0; j < 16; j++) vc[j] = validsm[sub * 16 + j];

    float mi = NEG_INF_F, mt = NEG_INF_F;
    #pragma unroll
    for (int j = 0; j < 16; j++)
        if (vc[j]) { mi = fmaxf(mi, im[j]); mt = fmaxf(mt, tx[j]); }
    #pragma unroll
    for (int o = 4; o; o >>= 1) {
        mi = fmaxf(mi, __shfl_xor_sync(0xffffffffu, mi, o, 8));
        mt = fmaxf(mt, __shfl_xor_sync(0xffffffffu, mt, o, 8));
    }
    float si = 0.f, st = 0.f;
    #pragma unroll
    for (int j = 0; j < 16; j++)
        if (vc[j]) { si += __expf(im[j] - mi); st += __expf(tx[j] - mt); }
    #pragma unroll
    for (int o = 4; o; o >>= 1) {
        si += __shfl_xor_sync(0xffffffffu, si, o, 8);
        st += __shfl_xor_sync(0xffffffffu, st, o, 8);
    }
    float lsei = logf(si) + mi;
    float lset = logf(st) + mt;

    float kl = 0.f;
    #pragma unroll
    for (int j = 0; j < 16; j++) {
        if (vc[j]) {
            float ilp = im[j] - lsei;
            float tlp = tx[j] - lset;
            kl += __expf(tlp) * (tlp - ilp) + __expf(ilp) * (ilp - tlp);
        }
    }
    #pragma unroll
    for (int o = 4; o; o >>= 1) kl += __shfl_xor_sync(0xffffffffu, kl, o, 8);
    if (sub == 0) rowklsm[row] = validsm[row] ? kl : 0.f;
    __syncthreads();

    float vkl = (t < BB) ? rowklsm[t] : 0.f;
    float vnv = (t < BB) ? (float)validsm[t] : 0.f;
    float rkl = blockReduceSum(vkl);
    if (t == 0) srkl = rkl;
    float rnv = blockReduceSum(vnv);
    if (t == 0) {
        int n = (int)(rnv + 0.5f);
        g_alignpart[p] = (n > 0) ? 0.5f * srkl / (float)n : 0.f;
    }
}

// ---------------- 5. fused neg-reduce + positive distances ----------------
__global__ void reduce_pos_kernel(const float* __restrict__ feat,
                                  const float* __restrict__ centers,
                                  const int* __restrict__ ci) {
    int pb = blockIdx.x;
    int p = pb / BB, b = pb % BB;
    int t = threadIdx.x, lane = t & 31, wid = t >> 5;

    float s = g_partial[((size_t)p * NTILES + t) * BB + b]
            + g_partial[((size_t)p * NTILES + t + 128) * BB + b];
    float rneg = blockReduceSum(s);
    if (t == 0) g_negsum[pb] = rneg;

    __shared__ float wsum[4];
    const float4* f = (const float4*)(feat + (size_t)pb * DD);
    float fn2v = g_fn2[pb];
    float part = 0.f;
    for (int k = wid; k < KK; k += 4) {
        int idx = ci[b * KK + k];
        const float4* c = (const float4*)(centers + ((size_t)p * NN + idx) * DD);
        float dot = 0.f, pn2 = 0.f;
        #pragma unroll
        for (int qq = lane; qq < DD / 4; qq += 32) {
            float4 a = f[qq], bv = c[qq];
            dot += a.x * bv.x + a.y * bv.y + a.z * bv.z + a.w * bv.w;
            pn2 += bv.x * bv.x + bv.y * bv.y + bv.z * bv.z + bv.w * bv.w;
        }
        #pragma unroll
        for (int o = 16; o; o >>= 1) {
            dot += __shfl_down_sync(0xffffffffu, dot, o);
            pn2 += __shfl_down_sync(0xffffffffu, pn2, o);
        }
        if (lane == 0) part += edist(fn2v + pn2 - 2.f * dot);
    }
    if (lane == 0) wsum[wid] = part;
    __syncthreads();
    if (t == 0) g_possum[pb] = wsum[0] + wsum[1] + wsum[2] + wsum[3];
}

// ---------------- 6. final combine + pos_vid gather ----------------
__global__ void final_kernel(const int* __restrict__ vid,
                             const int* __restrict__ ci,
                             float* __restrict__ out) {
    int b = threadIdx.x;
    for (int i = b; i < BB * KK; i += 128) out[3 + i] = (float)vid[ci[i]];

    __shared__ float sacc;
    if (b == 0) sacc = 0.f;
    __syncthreads();
    for (int p = 0; p < PP; p++) {
        float v = logf(g_negsum[p * BB + b]) - logf(g_possum[p * BB + b]);
        float r = blockReduceSum(v);
        if (b == 0) {
            float lp = r / (float)BB;
            if (isnan(lp)) lp = 0.f;
            sacc += lp;
        }
        __syncthreads();
    }
    if (b == 0) {
        float contrastive = sacc / (float)PP;
        float align = g_alignpart[0] + g_alignpart[1] + g_alignpart[2] + g_alignpart[3];
        out[0] = contrastive + KLW * align;
        out[1] = contrastive;
        out[2] = align;
    }
}

// ---------------- launch ----------------
extern "C" void kernel_launch(void* const* d_in, const int* in_sizes, int n_in,
                              void* d_out, int out_size) {
    const float* feature = (const float*)d_in[0];
    const float* text    = (const float*)d_in[1];
    const float* centers = (const float*)d_in[2];
    const int*   pos     = (const int*)d_in[3];
    const int*   ci      = (const int*)d_in[4];
    const int*   vid     = (const int*)d_in[5];
    float* out = (float*)d_out;

    cudaFuncSetAttribute(sim_gemm_kernel,
                         cudaFuncAttributeMaxDynamicSharedMemorySize, DSMEM_BYTES);

    prep_kernel<<<PP * BB, 128>>>(feature, text);
    mask_scatter_kernel<<<(BB * KK + BB + 255) / 256, 256>>>(ci, pos);
    sim_gemm_kernel<<<dim3(8, PP), 256, DSMEM_BYTES>>>();
    neg_bf16_kernel<<<dim3(NTILES, PP), 256>>>(centers);   // 4th: profiled
    fused_align_kernel<<<PP, 1024>>>();
    reduce_pos_kernel<<<PP * BB, 128>>>(feature, centers, ci);
    final_kernel<<<1, 128>>>(vid, ci, out);
}